// round 4
// baseline (speedup 1.0000x reference)
#include <cuda_runtime.h>
#include <cstdint>

// ROI max pool, reference semantics:
//   ro = r >> 1; amin = max(a-ro, 0); amax = a+ro; if (amax > LIM) amax = LIM-1;
//   bin i: [amin + (i*len)/8, amin + ((i+1)*len+7)/8)
// feature_map: (C=256, H=64, W=64) f32, W contiguous. out: (N, C, 8, 8) f32.
//
// block=128 (4 warps), grid=(N,16); each warp owns 4 channels of one ROI.
// Stage 1 (vectorized): abase = xmin&~3; lane = ci*8+xi owns the 16B chunk
//   [abase+4*xi, +4) of channel cbase+ci. Per bin-row: one LDG.128 + 4 FMNMX.
//   Boundary row cached in a float4 (adjacent bins overlap by <=1 row).
//   Each bin's colmax float4 is STS.128'd to sh[ph]; no sync yet.
// Stage 2: ONE __syncwarp, then lane=(ci,pw) reduces its x-bin for all 8 ph
//   (6 LDS + 5 predicated FMNMX each) and stores out[n][c][ph][pw].

namespace {
constexpr int Cdim  = 256;
constexpr int Wdim  = 64;
constexpr int Hdim  = 64;
constexpr int PLANE = Hdim * Wdim;   // 4096
constexpr int CHSTR = 44;            // floats per channel row in smem (fits span<=43+1)
constexpr int BINSTR = 4 * CHSTR;    // 176 floats per bin
}

template<bool WIDE>
__device__ __forceinline__
void roi_warp_work(const float* __restrict__ pbase, // fm + ch*PLANE + ymin*W + abase + xi*4
                   float* __restrict__ shw,         // this warp's smem: [8][4][44]
                   float* __restrict__ outw,        // out + ((n*C + cbase) << 6)
                   int leny, int lenx, int ax,      // ax = xmin - abase (0..3)
                   int lane, bool act0, bool act1)
{
    const float NEG_INF = __int_as_float(0xff800000);
    const int pw = lane & 7;
    const int ci = lane >> 3;
    const int sbase = ci * CHSTR + (lane & 7) * 4;   // this lane's STS slot offset

    float4 c0 = make_float4(NEG_INF, NEG_INF, NEG_INF, NEG_INF);
    float4 c1 = c0;                                   // wide-chunk cache
    int prev_re = -1;

    #pragma unroll
    for (int ph = 0; ph < 8; ph++) {
        const int rs = (ph * leny) >> 3;
        const int re = ((ph + 1) * leny + 7) >> 3;

        const bool seed = (rs < prev_re);
        const int  y0   = seed ? rs + 1 : rs;

        float4 m0 = seed ? c0 : make_float4(NEG_INF, NEG_INF, NEG_INF, NEG_INF);
        float4 m1;
        if (WIDE) m1 = seed ? c1 : make_float4(NEG_INF, NEG_INF, NEG_INF, NEG_INF);

        const float* p = pbase + (size_t)y0 * Wdim;
        #pragma unroll 2
        for (int yy = y0; yy < re; yy++, p += Wdim) {
            if (act0) {
                float4 v = __ldg((const float4*)p);
                m0.x = fmaxf(m0.x, v.x);
                m0.y = fmaxf(m0.y, v.y);
                m0.z = fmaxf(m0.z, v.z);
                m0.w = fmaxf(m0.w, v.w);
                c0 = v;
            }
            if (WIDE) {
                if (act1) {
                    float4 v = __ldg((const float4*)(p + 32));
                    m1.x = fmaxf(m1.x, v.x);
                    m1.y = fmaxf(m1.y, v.y);
                    m1.z = fmaxf(m1.z, v.z);
                    m1.w = fmaxf(m1.w, v.w);
                    c1 = v;
                }
            }
        }
        // restore cache semantics for empty (fully-seeded) bins:
        if (y0 == re && seed) { /* cache unchanged */ }
        prev_re = re;

        float* sb = shw + ph * BINSTR;
        *(float4*)(sb + sbase) = m0;
        if (WIDE) {
            if ((lane & 7) < 3)
                *(float4*)(sb + sbase + 32) = m1;
        }
    }

    __syncwarp();

    // stage 2: lane (ci, pw) for all 8 bins
    const int csrel = (pw * lenx) >> 3;
    const int width = (((pw + 1) * lenx + 7) >> 3) - csrel;   // 1..6
    const float* s0 = shw + ci * CHSTR + ax + csrel;

    #pragma unroll
    for (int ph = 0; ph < 8; ph++) {
        const float* s = s0 + ph * BINSTR;
        float m = s[0];
        #pragma unroll
        for (int j = 1; j < 6; j++) {
            float v = s[j];                   // in-bounds: ax+csrel+5 <= 43
            if (j < width) m = fmaxf(m, v);
        }
        outw[(ci << 6) + (ph << 3) + pw] = m;
    }
}

__global__ __launch_bounds__(128)
void roi_pool_kernel(const float* __restrict__ fm,
                     const int4* __restrict__ rois,
                     float* __restrict__ out)
{
    const int n     = blockIdx.x;
    const int tid   = threadIdx.x;
    const int warp  = tid >> 5;
    const int lane  = tid & 31;
    const int cbase = blockIdx.y * 16 + warp * 4;

    const int4 r = rois[n];
    const int yc = r.x, xc = r.y, rh = r.z, rw = r.w;
    const int roy = rh >> 1, rox = rw >> 1;

    int ymin = yc - roy; if (ymin < 0) ymin = 0;
    int ymax = yc + roy; if (ymax > Hdim) ymax = Hdim - 1;
    int xmin = xc - rox; if (xmin < 0) xmin = 0;
    int xmax = xc + rox; if (xmax > Wdim) xmax = Wdim - 1;

    const int leny  = ymax - ymin;
    const int lenx  = xmax - xmin;
    const int abase = xmin & ~3;
    const int ax    = xmin - abase;
    const int span  = xmax - abase;          // <= 43
    const int nchunks = (span + 3) >> 2;     // <= 11

    __shared__ float sh[4][8 * BINSTR];

    const int ci = lane >> 3;
    const int xi = lane & 7;
    const bool act0 = (abase + 4 * xi) < xmax;               // chunk xi active
    const bool act1 = (abase + 4 * (xi + 8)) < xmax;         // wide chunk xi+8

    const float* pbase = fm + (size_t)(cbase + ci) * PLANE
                            + (size_t)ymin * Wdim + abase + 4 * xi;
    float* outw = out + (((size_t)n * Cdim + cbase) << 6);

    if (nchunks > 8)
        roi_warp_work<true >(pbase, sh[warp], outw, leny, lenx, ax, lane, act0, act1);
    else
        roi_warp_work<false>(pbase, sh[warp], outw, leny, lenx, ax, lane, act0, act1);
}

extern "C" void kernel_launch(void* const* d_in, const int* in_sizes, int n_in,
                              void* d_out, int out_size)
{
    const float* fm   = (const float*)d_in[0];
    const int4*  rois = (const int4*)d_in[1];
    float*       out  = (float*)d_out;
    const int N = in_sizes[1] / 4;

    dim3 grid(N, 16);
    roi_pool_kernel<<<grid, 128>>>(fm, rois, out);
}

// round 5
// speedup vs baseline: 1.0984x; 1.0984x over previous
#include <cuda_runtime.h>
#include <cstdint>

// ROI max pool, reference semantics:
//   ro = r >> 1; amin = max(a-ro, 0); amax = a+ro; if (amax > LIM) amax = LIM-1;
//   bin i: [amin + (i*len)/8, amin + ((i+1)*len+7)/8)
// feature_map: (C=256, H=64, W=64) f32, W contiguous. out: (N, C, 8, 8) f32.
//
// block=128 (4 warps), grid=(16, N). Warp handles 4 channels of one ROI.
// Stage 1: lanes = x (coalesced LDG.32 x4 for MLP), column max over y-bin rows,
//          boundary row cached (adjacent bins overlap by <=1 row).
// Stage 2: ping-pong smem with ONE syncwarp per bin (the WAR hazard at ph+2 is
//          already ordered by the intervening sync at ph+1); lane = ci*8+pw
//          reduces its x-bin (unrolled, predicated) and writes out[n][c][ph][pw].

namespace {
constexpr int Cdim  = 256;
constexpr int Wdim  = 64;
constexpr int Hdim  = 64;
constexpr int PLANE = Hdim * Wdim;  // 4096
}

template<bool WIDE>
__device__ __forceinline__
void roi_warp_work(const float* __restrict__ base,  // fm + c*PLANE + ymin*W + xmin + lane
                   float* __restrict__ shw,         // this warp's smem: [2][4][72]
                   float* __restrict__ outw,        // out + ((n*C + cbase) << 6)
                   int leny, int lenx, int lane)
{
    const float NEG_INF = __int_as_float(0xff800000);
    const int pw = lane & 7;
    const int ci = lane >> 3;
    const int csrel = (pw * lenx) >> 3;
    const int width = (((pw + 1) * lenx + 7) >> 3) - csrel;   // 1..6

    const bool a0 = lane < lenx;
    const bool a1 = WIDE && ((lane + 32) < lenx);

    // boundary-row cache (narrow path only)
    float l0 = NEG_INF, l1 = NEG_INF, l2 = NEG_INF, l3 = NEG_INF;
    int prev_re = -1;

    #pragma unroll
    for (int ph = 0; ph < 8; ph++) {
        const int rs = (ph * leny) >> 3;
        const int re = ((ph + 1) * leny + 7) >> 3;

        float m0, m1, m2, m3;
        float m01 = NEG_INF, m11 = NEG_INF, m21 = NEG_INF, m31 = NEG_INF;

        int y0 = rs;
        if (!WIDE) {
            const bool seed = (rs < prev_re);        // overlap row already loaded
            m0 = seed ? l0 : NEG_INF;
            m1 = seed ? l1 : NEG_INF;
            m2 = seed ? l2 : NEG_INF;
            m3 = seed ? l3 : NEG_INF;
            y0 = seed ? rs + 1 : rs;
        } else {
            m0 = m1 = m2 = m3 = NEG_INF;
        }

        // row regs start from cache so an empty (fully-seeded) bin keeps it valid
        float v0 = l0, v1 = l1, v2 = l2, v3 = l3;

        const float* p = base + (size_t)y0 * Wdim;
        for (int yy = y0; yy < re; yy++, p += Wdim) {
            if (a0) {
                v0 = __ldg(p);
                v1 = __ldg(p + PLANE);
                v2 = __ldg(p + 2 * PLANE);
                v3 = __ldg(p + 3 * PLANE);
                m0 = fmaxf(m0, v0);
                m1 = fmaxf(m1, v1);
                m2 = fmaxf(m2, v2);
                m3 = fmaxf(m3, v3);
            }
            if (WIDE) {
                if (a1) {
                    m01 = fmaxf(m01, __ldg(p + 32));
                    m11 = fmaxf(m11, __ldg(p + PLANE + 32));
                    m21 = fmaxf(m21, __ldg(p + 2 * PLANE + 32));
                    m31 = fmaxf(m31, __ldg(p + 3 * PLANE + 32));
                }
            }
        }

        if (!WIDE) {
            l0 = v0; l1 = v1; l2 = v2; l3 = v3;
            prev_re = re;
        }

        // ---- stage 2 (ping-pong; single sync per bin) ----
        // WAR safety: LDS of buffer (ph&1) at bin ph precedes (program order)
        // the syncwarp at bin ph+1, which precedes STS at bin ph+2.
        float* sb = shw + (ph & 1) * (4 * 72);
        sb[0 * 72 + lane] = m0;
        sb[1 * 72 + lane] = m1;
        sb[2 * 72 + lane] = m2;
        sb[3 * 72 + lane] = m3;
        if (WIDE) {
            sb[0 * 72 + lane + 32] = m01;
            sb[1 * 72 + lane + 32] = m11;
            sb[2 * 72 + lane + 32] = m21;
            sb[3 * 72 + lane + 32] = m31;
        }
        __syncwarp();

        float m = NEG_INF;
        const float* s = sb + ci * 72 + csrel;
        #pragma unroll
        for (int j = 0; j < 6; j++) {
            float v = s[j];                 // in-bounds loads (csrel<=35, 35+5<72)
            if (j < width) m = fmaxf(m, v); // stale slots masked
        }

        outw[(ci << 6) + (ph << 3) + pw] = m;
    }
}

__global__ __launch_bounds__(128)
void roi_pool_kernel(const float* __restrict__ fm,
                     const int4* __restrict__ rois,
                     float* __restrict__ out)
{
    const int n    = blockIdx.y;
    const int tid  = threadIdx.x;
    const int warp = tid >> 5;
    const int lane = tid & 31;
    const int cbase = blockIdx.x * 16 + warp * 4;

    const int4 r = rois[n];
    const int yc = r.x, xc = r.y, rh = r.z, rw = r.w;
    const int roy = rh >> 1, rox = rw >> 1;

    int ymin = yc - roy; if (ymin < 0) ymin = 0;
    int ymax = yc + roy; if (ymax > Hdim) ymax = Hdim - 1;
    int xmin = xc - rox; if (xmin < 0) xmin = 0;
    int xmax = xc + rox; if (xmax > Wdim) xmax = Wdim - 1;

    const int leny = ymax - ymin;
    const int lenx = xmax - xmin;

    __shared__ float sh[4][2 * 4 * 72];

    const float* base = fm + (size_t)cbase * PLANE + (size_t)ymin * Wdim + xmin + lane;
    float* outw = out + (((size_t)n * Cdim + cbase) << 6);

    if (lenx > 32)
        roi_warp_work<true >(base, sh[warp], outw, leny, lenx, lane);
    else
        roi_warp_work<false>(base, sh[warp], outw, leny, lenx, lane);
}

extern "C" void kernel_launch(void* const* d_in, const int* in_sizes, int n_in,
                              void* d_out, int out_size)
{
    const float* fm   = (const float*)d_in[0];
    const int4*  rois = (const int4*)d_in[1];
    float*       out  = (float*)d_out;
    const int N = in_sizes[1] / 4;

    dim3 grid(16, N);
    roi_pool_kernel<<<grid, 128>>>(fm, rois, out);
}

// round 6
// speedup vs baseline: 1.2104x; 1.1019x over previous
#include <cuda_runtime.h>
#include <cstdint>

// ROI max pool via 2D sparse tables.
//   ro = r >> 1; amin = max(a-ro,0); amax = a+ro; if (amax > LIM) amax = LIM-1;
//   bin i: [amin + (i*len)/8, amin + ((i+1)*len+7)/8)  -- width always in [1,6]
// fm: (C=256, H=64, W=64) f32. out: (N, C, 8, 8) f32.
//
// Precompute (build_tables): TB[ky][kx][y][x][c] = max over fm[c][y..y+2^ky)[x..x+2^kx)
//   (edge-clamped; clamped entries never used by queries). Channel-innermost layout
//   -> a warp of 32 consecutive channels reads exactly one 128B line per corner.
// Main: out[n][c][ph][pw] = max of 4 corner loads from table (ky(r_y), kx(r_x)).
//   Windows [y0,y0+2^ky) and [y1=re-2^ky, ...) cover the bin since 2^ky<=r<=2*2^ky.
//   Results staged in smem [64][33] (conflict-free), then one contiguous 8KB
//   coalesced store per warp (out rows for 32 consecutive channels are contiguous).

namespace {
constexpr int Cdim  = 256;
constexpr int Hdim  = 64;
constexpr int Wdim  = 64;
constexpr int PLANE = Hdim * Wdim;              // 4096
constexpr int LVL   = PLANE * Cdim;             // floats per table level = 1,048,576
constexpr int LVLB  = LVL * 4;                  // bytes per level = 4 MB
constexpr int YSTRB = Wdim * Cdim * 4;          // byte stride per y = 65536
constexpr int XSTRB = Cdim * 4;                 // byte stride per x = 1024
}

__device__ float TB[9 * LVL];                   // 36 MB scratch tables

// ---------------- table builder ----------------
// grid (8 c-chunks, 32 y-slabs), block 256. Slab = 2 output y rows; needs rows
// y0..y0+4 (clamped). Smem holds them transposed: S[row][x][c'] (33 pad -> no conflicts).
__global__ __launch_bounds__(256)
void build_tables(const float* __restrict__ fm)
{
    const int c0 = blockIdx.x * 32;
    const int y0 = blockIdx.y * 2;

    __shared__ float S[5][64][33];

    // load 5 (clamped) rows x 64 x x 32 c, coalesced over x
    for (int idx = threadIdx.x; idx < 5 * 64 * 32; idx += 256) {
        const int row = idx >> 11;               // 0..4
        const int cc  = (idx >> 6) & 31;
        const int x   = idx & 63;
        int gy = y0 + row; if (gy > 63) gy = 63;
        S[row][x][cc] = fm[(size_t)(c0 + cc) * PLANE + gy * Wdim + x];
    }
    __syncthreads();

    const int lane = threadIdx.x & 31;
    const int warp = threadIdx.x >> 5;

    // 128 points (yy in 0..1, x in 0..63); 16 per warp; lane = channel
    for (int p = warp * 16; p < warp * 16 + 16; p++) {
        const int yy = p >> 6;
        const int x  = p & 63;
        const int x1 = x + 1 > 63 ? 63 : x + 1;
        const int x2 = x + 2 > 63 ? 63 : x + 2;
        const int x3 = x + 3 > 63 ? 63 : x + 3;

        float v00 = S[yy    ][x][lane], v01 = S[yy    ][x1][lane],
              v02 = S[yy    ][x2][lane], v03 = S[yy    ][x3][lane];
        float v10 = S[yy + 1][x][lane], v11 = S[yy + 1][x1][lane],
              v12 = S[yy + 1][x2][lane], v13 = S[yy + 1][x3][lane];
        float v20 = S[yy + 2][x][lane], v21 = S[yy + 2][x1][lane],
              v22 = S[yy + 2][x2][lane], v23 = S[yy + 2][x3][lane];
        float v30 = S[yy + 3][x][lane], v31 = S[yy + 3][x1][lane],
              v32 = S[yy + 3][x2][lane], v33 = S[yy + 3][x3][lane];

        // x-levels per row: X1 = 2 cols, X2 = 4 cols
        const float X1_0 = fmaxf(v00, v01), X2_0 = fmaxf(X1_0, fmaxf(v02, v03));
        const float X1_1 = fmaxf(v10, v11), X2_1 = fmaxf(X1_1, fmaxf(v12, v13));
        const float X1_2 = fmaxf(v20, v21), X2_2 = fmaxf(X1_2, fmaxf(v22, v23));
        const float X1_3 = fmaxf(v30, v31), X2_3 = fmaxf(X1_3, fmaxf(v32, v33));

        float t[9];
        t[0] = v00;                       // (ky0,kx0)
        t[1] = X1_0;                      // (ky0,kx1)
        t[2] = X2_0;                      // (ky0,kx2)
        t[3] = fmaxf(v00, v10);           // (ky1,kx0)
        t[4] = fmaxf(X1_0, X1_1);         // (ky1,kx1)
        t[5] = fmaxf(X2_0, X2_1);         // (ky1,kx2)
        t[6] = fmaxf(t[3], fmaxf(v20, v30));
        t[7] = fmaxf(t[4], fmaxf(X1_2, X1_3));
        t[8] = fmaxf(t[5], fmaxf(X2_2, X2_3));

        float* o = TB + ((size_t)(y0 + yy) * Wdim + x) * Cdim + c0 + lane;
        #pragma unroll
        for (int i = 0; i < 9; i++) { *o = t[i]; o += LVL; }
    }
}

// ---------------- main kernel ----------------
// grid (2, N), block 128 (4 warps). Warp = (n, 32-channel block cb = bx*4+warp).
__global__ __launch_bounds__(128)
void roi_pool_main(const int4* __restrict__ rois, float* __restrict__ out)
{
    const int n    = blockIdx.y;
    const int warp = threadIdx.x >> 5;
    const int lane = threadIdx.x & 31;
    const int cb   = blockIdx.x * 4 + warp;     // 0..7

    const int4 r = rois[n];
    const int yc = r.x, xc = r.y, rh = r.z, rw = r.w;
    const int roy = rh >> 1, rox = rw >> 1;

    int ymin = yc - roy; if (ymin < 0) ymin = 0;
    int ymax = yc + roy; if (ymax > Hdim) ymax = Hdim - 1;
    int xmin = xc - rox; if (xmin < 0) xmin = 0;
    int xmax = xc + rox; if (xmax > Wdim) xmax = Wdim - 1;

    const int leny = ymax - ymin;
    const int lenx = xmax - xmin;

    __shared__ float stage[4][64][33];
    float* st = &stage[warp][0][0];

    // per-pw byte offsets (kx-table select + x positions), uniform across lanes
    int pxb0[8], pxb1[8];
    #pragma unroll
    for (int pw = 0; pw < 8; pw++) {
        const int cs = (pw * lenx) >> 3;
        const int ce = ((pw + 1) * lenx + 7) >> 3;
        const int rx = ce - cs;                       // 1..6
        const int kx = (rx >= 4) ? 2 : (rx >= 2 ? 1 : 0);
        pxb0[pw] = kx * LVLB + (xmin + cs) * XSTRB;
        pxb1[pw] = kx * LVLB + (xmin + ce - (1 << kx)) * XSTRB;
    }

    const char* B = (const char*)TB + ((size_t)cb * 32 + lane) * 4;

    #pragma unroll
    for (int ph = 0; ph < 8; ph++) {
        const int rs = (ph * leny) >> 3;
        const int re = ((ph + 1) * leny + 7) >> 3;
        const int ry = re - rs;                       // 1..6
        const int ky = (ry >= 4) ? 2 : (ry >= 2 ? 1 : 0);
        const int pya0 = ky * 3 * LVLB + (ymin + rs) * YSTRB;
        const int pya1 = ky * 3 * LVLB + (ymin + re - (1 << ky)) * YSTRB;

        #pragma unroll
        for (int pw = 0; pw < 8; pw++) {
            const float v00 = *(const float*)(B + pya0 + pxb0[pw]);
            const float v01 = *(const float*)(B + pya0 + pxb1[pw]);
            const float v10 = *(const float*)(B + pya1 + pxb0[pw]);
            const float v11 = *(const float*)(B + pya1 + pxb1[pw]);
            st[(ph * 8 + pw) * 33 + lane] = fmaxf(fmaxf(v00, v01), fmaxf(v10, v11));
        }
    }
    __syncwarp();

    // coalesced writeback: out rows for channels cb*32..cb*32+31 are 8KB contiguous
    float* o = out + (size_t)n * (Cdim * 64) + cb * 32 * 64;
    #pragma unroll
    for (int i = 0; i < 64; i++) {
        const int g   = i * 32 + lane;       // 0..2047
        const int cc  = g >> 6;              // channel within block
        const int bin = g & 63;
        o[g] = st[bin * 33 + cc];
    }
}

extern "C" void kernel_launch(void* const* d_in, const int* in_sizes, int n_in,
                              void* d_out, int out_size)
{
    const float* fm   = (const float*)d_in[0];
    const int4*  rois = (const int4*)d_in[1];
    float*       out  = (float*)d_out;
    const int N = in_sizes[1] / 4;

    build_tables<<<dim3(8, 32), 256>>>(fm);
    roi_pool_main<<<dim3(2, N), 128>>>(rois, out);
}

// round 8
// speedup vs baseline: 1.6951x; 1.4005x over previous
#include <cuda_runtime.h>
#include <cstdint>

// ROI max pool via 2D sparse tables (log-max), round 8 (= R7 resubmit; infra failed).
//   ro = r >> 1; amin = max(a-ro,0); amax = a+ro; if (amax > LIM) amax = LIM-1;
//   bin i: [amin + (i*len)/8, amin + ((i+1)*len+7)/8)  -- width always in [1,6]
// fm: (C=256, H=64, W=64) f32. out: (N, C, 8, 8) f32.
//
// build_tables: TB[ky*3+kx][y][x][c] = max over fm[c][y..y+2^ky)[x..x+2^kx)
//   (edge-clamped; clamped entries never consumed). Channel-innermost.
// roi_pool_main: warp = (cb, ph-half). lane = pwsub*8 + cquad; each lane
//   loads float4 (4 channels) per corner -> 4 LDG.128 per 4-bin group, max
//   accumulated in-lane. 16-bin smem staging [16][36] (aligned, conflict-free),
//   coalesced chunk writeback.

namespace {
constexpr int Cdim  = 256;
constexpr int Hdim  = 64;
constexpr int Wdim  = 64;
constexpr int PLANE = Hdim * Wdim;              // 4096
constexpr int LVL   = PLANE * Cdim;             // floats per table level
constexpr int LVLB  = LVL * 4;                  // 4 MB per level
constexpr int YSTRB = Wdim * Cdim * 4;          // 65536
constexpr int XSTRB = Cdim * 4;                 // 1024
}

__device__ float TB[9 * LVL];                   // 36 MB scratch tables

// ---------------- table builder ----------------
__global__ __launch_bounds__(256)
void build_tables(const float* __restrict__ fm)
{
    const int c0 = blockIdx.x * 32;
    const int y0 = blockIdx.y * 2;

    __shared__ float S[5][64][33];

    for (int idx = threadIdx.x; idx < 5 * 64 * 32; idx += 256) {
        const int row = idx >> 11;
        const int cc  = (idx >> 6) & 31;
        const int x   = idx & 63;
        int gy = y0 + row; if (gy > 63) gy = 63;
        S[row][x][cc] = fm[(size_t)(c0 + cc) * PLANE + gy * Wdim + x];
    }
    __syncthreads();

    const int lane = threadIdx.x & 31;
    const int warp = threadIdx.x >> 5;

    for (int p = warp * 16; p < warp * 16 + 16; p++) {
        const int yy = p >> 6;
        const int x  = p & 63;
        const int x1 = x + 1 > 63 ? 63 : x + 1;
        const int x2 = x + 2 > 63 ? 63 : x + 2;
        const int x3 = x + 3 > 63 ? 63 : x + 3;

        float v00 = S[yy    ][x][lane], v01 = S[yy    ][x1][lane],
              v02 = S[yy    ][x2][lane], v03 = S[yy    ][x3][lane];
        float v10 = S[yy + 1][x][lane], v11 = S[yy + 1][x1][lane],
              v12 = S[yy + 1][x2][lane], v13 = S[yy + 1][x3][lane];
        float v20 = S[yy + 2][x][lane], v21 = S[yy + 2][x1][lane],
              v22 = S[yy + 2][x2][lane], v23 = S[yy + 2][x3][lane];
        float v30 = S[yy + 3][x][lane], v31 = S[yy + 3][x1][lane],
              v32 = S[yy + 3][x2][lane], v33 = S[yy + 3][x3][lane];

        const float X1_0 = fmaxf(v00, v01), X2_0 = fmaxf(X1_0, fmaxf(v02, v03));
        const float X1_1 = fmaxf(v10, v11), X2_1 = fmaxf(X1_1, fmaxf(v12, v13));
        const float X1_2 = fmaxf(v20, v21), X2_2 = fmaxf(X1_2, fmaxf(v22, v23));
        const float X1_3 = fmaxf(v30, v31), X2_3 = fmaxf(X1_3, fmaxf(v32, v33));

        float t[9];
        t[0] = v00;
        t[1] = X1_0;
        t[2] = X2_0;
        t[3] = fmaxf(v00, v10);
        t[4] = fmaxf(X1_0, X1_1);
        t[5] = fmaxf(X2_0, X2_1);
        t[6] = fmaxf(t[3], fmaxf(v20, v30));
        t[7] = fmaxf(t[4], fmaxf(X1_2, X1_3));
        t[8] = fmaxf(t[5], fmaxf(X2_2, X2_3));

        float* o = TB + ((size_t)(y0 + yy) * Wdim + x) * Cdim + c0 + lane;
        #pragma unroll
        for (int i = 0; i < 9; i++) { *o = t[i]; o += LVL; }
    }
}

// ---------------- main kernel ----------------
// grid (4, N), block 128. bx: cb-group = bx>>1, ph-half = bx&1.
// Warp handles channel block cb = (bx>>1)*4 + warp, bins ph in [phh*4, phh*4+4).
__global__ __launch_bounds__(128)
void roi_pool_main(const int4* __restrict__ rois, float* __restrict__ out)
{
    const int n    = blockIdx.y;
    const int warp = threadIdx.x >> 5;
    const int lane = threadIdx.x & 31;
    const int cb   = (blockIdx.x >> 1) * 4 + warp;   // 0..7
    const int phh  = blockIdx.x & 1;                 // ph half

    const int4 r = rois[n];
    const int yc = r.x, xc = r.y, rh = r.z, rw = r.w;
    const int roy = rh >> 1, rox = rw >> 1;

    int ymin = yc - roy; if (ymin < 0) ymin = 0;
    int ymax = yc + roy; if (ymax > Hdim) ymax = Hdim - 1;
    int xmin = xc - rox; if (xmin < 0) xmin = 0;
    int xmax = xc + rox; if (xmax > Wdim) xmax = Wdim - 1;

    const int leny = ymax - ymin;
    const int lenx = xmax - xmin;

    const int pwsub = lane >> 3;                 // 0..3
    const int cquad = lane & 7;                  // 0..7
    const int chb   = (cb * 32 + cquad * 4) * 4; // byte offset of lane's channels

    // x corner byte-offsets (incl. kx level term) for the two pw steps
    int xb0[2], xb1[2];
    #pragma unroll
    for (int s = 0; s < 2; s++) {
        const int pw = s * 4 + pwsub;
        const int cs = (pw * lenx) >> 3;
        const int ce = ((pw + 1) * lenx + 7) >> 3;
        const int rx = ce - cs;                            // 1..6
        const int kx = (rx >= 4) ? 2 : (rx >= 2 ? 1 : 0);  // 2^kx <= rx <= 2*2^kx
        xb0[s] = kx * LVLB + (xmin + cs) * XSTRB + chb;
        xb1[s] = kx * LVLB + (xmin + ce - (1 << kx)) * XSTRB + chb;
    }

    __shared__ float stage[4][16 * 36];
    float* st = stage[warp];

    const char* Bp = (const char*)TB;
    float* o = out + (size_t)n * (Cdim * 64) + cb * 32 * 64;

    #pragma unroll
    for (int php = 0; php < 2; php++) {          // two 16-bin chunks per warp
        #pragma unroll
        for (int ph2 = 0; ph2 < 2; ph2++) {
            const int ph = phh * 4 + php * 2 + ph2;
            const int rs = (ph * leny) >> 3;
            const int re = ((ph + 1) * leny + 7) >> 3;
            const int ry = re - rs;                            // 1..6
            const int ky = (ry >= 4) ? 2 : (ry >= 2 ? 1 : 0);
            const int ya0 = ky * 3 * LVLB + (ymin + rs) * YSTRB;
            const int ya1 = ky * 3 * LVLB + (ymin + re - (1 << ky)) * YSTRB;

            #pragma unroll
            for (int s = 0; s < 2; s++) {
                const float4 v00 = __ldg((const float4*)(Bp + ya0 + xb0[s]));
                const float4 v01 = __ldg((const float4*)(Bp + ya0 + xb1[s]));
                const float4 v10 = __ldg((const float4*)(Bp + ya1 + xb0[s]));
                const float4 v11 = __ldg((const float4*)(Bp + ya1 + xb1[s]));
                float4 m;
                m.x = fmaxf(fmaxf(v00.x, v01.x), fmaxf(v10.x, v11.x));
                m.y = fmaxf(fmaxf(v00.y, v01.y), fmaxf(v10.y, v11.y));
                m.z = fmaxf(fmaxf(v00.z, v01.z), fmaxf(v10.z, v11.z));
                m.w = fmaxf(fmaxf(v00.w, v01.w), fmaxf(v10.w, v11.w));

                const int bl = ph2 * 8 + s * 4 + pwsub;        // 0..15
                *(float4*)(st + bl * 36 + cquad * 4) = m;
            }
        }
        __syncwarp();

        // coalesced chunk writeback: 16 bins x 32 channels
        const int base = (phh * 2 + php) * 16;   // global bin offset of chunk
        #pragma unroll
        for (int i = 0; i < 16; i++) {
            const int g   = i * 32 + lane;
            const int cc  = g >> 4;              // channel within block (0..31)
            const int b16 = g & 15;              // bin within chunk
            o[cc * 64 + base + b16] = st[b16 * 36 + cc];
        }
        __syncwarp();                            // WAR before next chunk's stores
    }
}

extern "C" void kernel_launch(void* const* d_in, const int* in_sizes, int n_in,
                              void* d_out, int out_size)
{
    const float* fm   = (const float*)d_in[0];
    const int4*  rois = (const int4*)d_in[1];
    float*       out  = (float*)d_out;
    const int N = in_sizes[1] / 4;

    build_tables<<<dim3(8, 32), 256>>>(fm);
    roi_pool_main<<<dim3(4, N), 128>>>(rois, out);
}